// round 3
// baseline (speedup 1.0000x reference)
#include <cuda_runtime.h>
#include <cuda_bf16.h>
#include <cstdint>

#define DIM 128
#define NLAYERS 4
#define NQ 7
#define TILE_M 128
#define NTHREADS 256
#define KPAD 136      // bf16 elems per smem row (128 + 8 pad -> conflict-free ldmatrix)

// ---- device globals (no allocation allowed) ----
__device__ float2 g_U[DIM * DIM];             // U[k][j]
__device__ float2 g_UT[DIM * DIM];            // U^T[j][k]
__device__ __nv_bfloat16 g_Whi[DIM * DIM];    // A hi split, [n][k]
__device__ __nv_bfloat16 g_Wlo[DIM * DIM];    // A lo split, [n][k]

__device__ __forceinline__ float2 cmul(float2 a, float2 b) {
    return make_float2(a.x * b.x - a.y * b.y, a.x * b.y + a.y * b.x);
}

// ---------------------------------------------------------------------------
// Kernel 1: build U. One block per basis column j. Gate matrices precomputed
// once per block by threads 0..27 (single sincos round, not 28 serial ones).
// ---------------------------------------------------------------------------
__global__ void build_u_kernel(const float* __restrict__ w) {
    __shared__ float2 col[DIM];
    __shared__ float2 gm[NLAYERS * NQ][4];
    const int j = blockIdx.x;
    const int t = threadIdx.x;  // 128 threads

    if (t < NLAYERS * NQ) {
        const float phi = w[t * 3 + 0];
        const float th  = w[t * 3 + 1];
        const float om  = w[t * 3 + 2];
        float sh, ch; sincosf(0.5f * th, &sh, &ch);
        float sap, cap, sam, cam;
        sincosf(0.5f * (phi + om), &sap, &cap);
        sincosf(0.5f * (phi - om), &sam, &cam);
        gm[t][0] = make_float2( cap * ch, -sap * ch);
        gm[t][1] = make_float2(-cam * sh, -sam * sh);
        gm[t][2] = make_float2( cam * sh, -sam * sh);
        gm[t][3] = make_float2( cap * ch,  sap * ch);
    }
    col[t] = make_float2(t == j ? 1.f : 0.f, 0.f);
    __syncthreads();

    for (int l = 0; l < NLAYERS; l++) {
        for (int q = 0; q < NQ; q++) {
            const int g = l * NQ + q;
            const float2 u00 = gm[g][0], u01 = gm[g][1];
            const float2 u10 = gm[g][2], u11 = gm[g][3];
            const int bit = 1 << (6 - q);
            if (!(t & bit)) {
                const float2 a0 = col[t];
                const float2 a1 = col[t | bit];
                float2 m00 = cmul(u00, a0), m01 = cmul(u01, a1);
                float2 m10 = cmul(u10, a0), m11 = cmul(u11, a1);
                col[t]       = make_float2(m00.x + m01.x, m00.y + m01.y);
                col[t | bit] = make_float2(m10.x + m11.x, m10.y + m11.y);
            }
            __syncthreads();
        }
        const int r = (l % (NQ - 1)) + 1;
        for (int c = 0; c < NQ; c++) {
            const int tg = (c + r) % NQ;
            const int cb = 1 << (6 - c);
            const int tb = 1 << (6 - tg);
            if ((t & cb) && !(t & tb)) {
                const float2 tmp = col[t];
                col[t] = col[t | tb];
                col[t | tb] = tmp;
            }
            __syncthreads();
        }
    }
    g_U[t * DIM + j] = col[t];     // [k][j]
    g_UT[j * DIM + t] = col[t];    // [j][k], coalesced
}

// ---------------------------------------------------------------------------
// Kernel 2: A[i][j] = sum_k d_k * Re( conj(U[k][i]) U[k][j] ), bf16 hi/lo split
// ---------------------------------------------------------------------------
__global__ void build_w_kernel() {
    __shared__ float2 ui[DIM];
    const int i = blockIdx.x;
    const int j = threadIdx.x;
    ui[j] = g_UT[i * DIM + j];  // coalesced
    __syncthreads();
    float acc = 0.f;
    for (int k = 0; k < DIM; k++) {
        const float dk = (((k >> 6) ^ k) & 1) ? -1.f : 1.f;
        const float2 uj = g_U[k * DIM + j];  // coalesced across j
        acc += dk * (ui[k].x * uj.x + ui[k].y * uj.y);
    }
    const __nv_bfloat16 h = __float2bfloat16(acc);
    const __nv_bfloat16 lo = __float2bfloat16(acc - __bfloat162float(h));
    g_Whi[i * DIM + j] = h;
    g_Wlo[i * DIM + j] = lo;
}

// ---------------------------------------------------------------------------
// Main kernel
// ---------------------------------------------------------------------------
#define SM_ZHI   0
#define SM_ZLO   34816
#define SM_WHI   69632
#define SM_WLO   104448
#define SM_STAGE 139264   // 128x128 fp32 raw tile (cp.async target)
#define SM_PD    204800   // dot partials, 128x2 f32
#define SM_PS    205824   // sq partials,  128x2 f32
#define SM_TOTAL 206848

__device__ __forceinline__ void ldsm4(uint32_t& r0, uint32_t& r1, uint32_t& r2,
                                      uint32_t& r3, uint32_t addr) {
    asm volatile("ldmatrix.sync.aligned.m8n8.x4.shared.b16 {%0,%1,%2,%3}, [%4];"
                 : "=r"(r0), "=r"(r1), "=r"(r2), "=r"(r3) : "r"(addr));
}
__device__ __forceinline__ void mma16816(float* d, const uint32_t* a, const uint32_t* b) {
    asm volatile(
        "mma.sync.aligned.m16n8k16.row.col.f32.bf16.bf16.f32 "
        "{%0,%1,%2,%3}, {%4,%5,%6,%7}, {%8,%9}, {%0,%1,%2,%3};"
        : "+f"(d[0]), "+f"(d[1]), "+f"(d[2]), "+f"(d[3])
        : "r"(a[0]), "r"(a[1]), "r"(a[2]), "r"(a[3]), "r"(b[0]), "r"(b[1]));
}
__device__ __forceinline__ uint32_t pack2bf(float a, float b) {
    return ((uint32_t)__bfloat16_as_ushort(__float2bfloat16(b)) << 16) |
           (uint32_t)__bfloat16_as_ushort(__float2bfloat16(a));
}
__device__ __forceinline__ void cp_async16(uint32_t saddr, const void* g) {
    asm volatile("cp.async.cg.shared.global [%0], [%1], 16;" :: "r"(saddr), "l"(g));
}

__global__ void __launch_bounds__(NTHREADS, 1)
vqa_main_kernel(const float* __restrict__ x, float* __restrict__ out, int ntiles) {
    extern __shared__ char smem[];
    const uint32_t sbase = (uint32_t)__cvta_generic_to_shared(smem);

    const int tid = threadIdx.x;
    const int lane = tid & 31;
    const int wid = tid >> 5;
    const int mi = wid & 3;   // m-stripe (32 rows)
    const int nh = wid >> 2;  // n-half (64 cols)

    // ---- prologue: start the first tile copy immediately ----
    {
        int t0 = blockIdx.x;
        if (t0 < ntiles) {
            const float* src = x + (size_t)t0 * (TILE_M * DIM) + tid * 4;
            #pragma unroll
            for (int i = 0; i < 16; i++)
                cp_async16(sbase + SM_STAGE + (uint32_t)((tid + i * 256) * 16),
                           src + i * 1024);
        }
        asm volatile("cp.async.commit_group;");
    }

    // ---- load W (A hi/lo) into padded smem, once per CTA ----
    {
        const uint2* whi_g = (const uint2*)g_Whi;
        const uint2* wlo_g = (const uint2*)g_Wlo;
        for (int idx = tid; idx < DIM * 32; idx += NTHREADS) {
            const int i = idx >> 5, c = idx & 31;
            *(uint2*)(smem + SM_WHI + i * (KPAD * 2) + c * 8) = whi_g[idx];
            *(uint2*)(smem + SM_WLO + i * (KPAD * 2) + c * 8) = wlo_g[idx];
        }
    }

    // ldmatrix lane base addresses (bytes)
    const uint32_t abase = sbase + SM_ZHI +
        (uint32_t)(((32 * mi + (lane & 15)) * KPAD + 8 * (lane >> 4)) * 2);
    const int rowL = (lane & 7) + ((lane >> 4) & 1) * 8;
    const int kL = ((lane >> 3) & 1) * 8;
    const uint32_t bbase = sbase + SM_WHI +
        (uint32_t)(((64 * nh + rowL) * KPAD + kL) * 2);

    float* pd = (float*)(smem + SM_PD);
    float* ps = (float*)(smem + SM_PS);

    for (int tile = blockIdx.x; tile < ntiles; tile += (int)gridDim.x) {
        asm volatile("cp.async.wait_group 0;");
        __syncthreads();

        // ---- convert: stage fp32 -> bf16 hi/lo split buffers ----
        #pragma unroll
        for (int rr = 0; rr < 16; rr++) {
            const int row = wid * 16 + rr;
            const float4 v = *(const float4*)(smem + SM_STAGE + row * 512 + lane * 16);
            const float hx = __bfloat162float(__float2bfloat16(v.x));
            const float hy = __bfloat162float(__float2bfloat16(v.y));
            const float hz = __bfloat162float(__float2bfloat16(v.z));
            const float hw = __bfloat162float(__float2bfloat16(v.w));
            *(uint2*)(smem + SM_ZHI + row * (KPAD * 2) + lane * 8) =
                make_uint2(pack2bf(hx, hy), pack2bf(hz, hw));
            *(uint2*)(smem + SM_ZLO + row * (KPAD * 2) + lane * 8) =
                make_uint2(pack2bf(v.x - hx, v.y - hy), pack2bf(v.z - hz, v.w - hw));
        }
        __syncthreads();

        // ---- prefetch next tile while we compute ----
        {
            const int nxt = tile + (int)gridDim.x;
            if (nxt < ntiles) {
                const float* src = x + (size_t)nxt * (TILE_M * DIM) + tid * 4;
                #pragma unroll
                for (int i = 0; i < 16; i++)
                    cp_async16(sbase + SM_STAGE + (uint32_t)((tid + i * 256) * 16),
                               src + i * 1024);
            }
            asm volatile("cp.async.commit_group;");
        }

        // ---- GEMM: K = 3 segments x 128 ----
        float d[2][8][4];
        #pragma unroll
        for (int mt = 0; mt < 2; mt++)
            #pragma unroll
            for (int nt = 0; nt < 8; nt++)
                #pragma unroll
                for (int q = 0; q < 4; q++) d[mt][nt][q] = 0.f;

        #pragma unroll
        for (int seg = 0; seg < 3; seg++) {
            const uint32_t zo = (seg == 1) ? (uint32_t)(SM_ZLO - SM_ZHI) : 0u;
            const uint32_t wo = (seg == 2) ? (uint32_t)(SM_WLO - SM_WHI) : 0u;
            #pragma unroll
            for (int kk = 0; kk < 8; kk++) {
                const uint32_t ko = (uint32_t)(kk * 32);  // 16 elems * 2B
                uint32_t a0[4], a1[4];
                ldsm4(a0[0], a0[1], a0[2], a0[3], abase + zo + ko);
                ldsm4(a1[0], a1[1], a1[2], a1[3], abase + zo + ko + 16 * KPAD * 2);
                uint32_t bfr[4][4];
                #pragma unroll
                for (int ntp = 0; ntp < 4; ntp++)
                    ldsm4(bfr[ntp][0], bfr[ntp][1], bfr[ntp][2], bfr[ntp][3],
                          bbase + wo + ko + (uint32_t)(ntp * 16 * KPAD * 2));
                #pragma unroll
                for (int ntp = 0; ntp < 4; ntp++) {
                    mma16816(d[0][2 * ntp + 0], a0, &bfr[ntp][0]);
                    mma16816(d[0][2 * ntp + 1], a0, &bfr[ntp][2]);
                    mma16816(d[1][2 * ntp + 0], a1, &bfr[ntp][0]);
                    mma16816(d[1][2 * ntp + 1], a1, &bfr[ntp][2]);
                }
            }
        }

        // ---- epilogue: out[m] = (y.x) / (x.x), x reconstructed as hi+lo ----
        const int tq = lane & 3;
        const int tr = lane >> 2;
        float racc[4] = {0.f, 0.f, 0.f, 0.f};
        float sacc[4] = {0.f, 0.f, 0.f, 0.f};
        #pragma unroll
        for (int mt = 0; mt < 2; mt++) {
            const int row0 = 32 * mi + 16 * mt + tr;
            #pragma unroll
            for (int nt = 0; nt < 8; nt++) {
                const int c = 64 * nh + 8 * nt + 2 * tq;
                const int o0 = (row0 * KPAD + c) * 2;
                const int o1 = ((row0 + 8) * KPAD + c) * 2;
                float2 h0 = __bfloat1622float2(*(__nv_bfloat162*)(smem + SM_ZHI + o0));
                float2 l0 = __bfloat1622float2(*(__nv_bfloat162*)(smem + SM_ZLO + o0));
                float2 h1 = __bfloat1622float2(*(__nv_bfloat162*)(smem + SM_ZHI + o1));
                float2 l1 = __bfloat1622float2(*(__nv_bfloat162*)(smem + SM_ZLO + o1));
                const float x0a = h0.x + l0.x, x0b = h0.y + l0.y;
                const float x1a = h1.x + l1.x, x1b = h1.y + l1.y;
                racc[2 * mt]     += d[mt][nt][0] * x0a + d[mt][nt][1] * x0b;
                racc[2 * mt + 1] += d[mt][nt][2] * x1a + d[mt][nt][3] * x1b;
                sacc[2 * mt]     += x0a * x0a + x0b * x0b;
                sacc[2 * mt + 1] += x1a * x1a + x1b * x1b;
            }
        }
        #pragma unroll
        for (int q = 0; q < 4; q++) {
            racc[q] += __shfl_xor_sync(0xffffffffu, racc[q], 1);
            racc[q] += __shfl_xor_sync(0xffffffffu, racc[q], 2);
            sacc[q] += __shfl_xor_sync(0xffffffffu, sacc[q], 1);
            sacc[q] += __shfl_xor_sync(0xffffffffu, sacc[q], 2);
        }
        if (tq == 0) {
            #pragma unroll
            for (int q = 0; q < 4; q++) {
                const int row = 32 * mi + 8 * q + tr;
                pd[row * 2 + nh] = racc[q];
                ps[row * 2 + nh] = sacc[q];
            }
        }
        __syncthreads();
        if (tid < TILE_M) {
            out[(size_t)tile * TILE_M + tid] =
                (pd[tid * 2] + pd[tid * 2 + 1]) / (ps[tid * 2] + ps[tid * 2 + 1]);
        }
    }
}

// ---------------------------------------------------------------------------
extern "C" void kernel_launch(void* const* d_in, const int* in_sizes, int n_in,
                              void* d_out, int out_size) {
    const float* x = (const float*)d_in[0];
    const float* w = (const float*)d_in[1];
    float* out = (float*)d_out;

    cudaFuncSetAttribute(vqa_main_kernel,
                         cudaFuncAttributeMaxDynamicSharedMemorySize, SM_TOTAL);

    build_u_kernel<<<DIM, DIM>>>(w);
    build_w_kernel<<<DIM, DIM>>>();

    const int rows = in_sizes[0] / DIM;
    const int ntiles = rows / TILE_M;
    vqa_main_kernel<<<152, NTHREADS, SM_TOTAL>>>(x, out, ntiles);
}

// round 8
// speedup vs baseline: 1.5734x; 1.5734x over previous
#include <cuda_runtime.h>
#include <cuda_bf16.h>
#include <cstdint>

#define DIM 128
#define NLAYERS 4
#define NQ 7
#define TILE_M 128
#define NTHREADS 256
#define KPAD 136      // bf16 elems per smem row (conflict-free ldmatrix)
#define XPAD 132      // fp32 elems per smem row

// ---- device globals ----
__device__ float2 g_U[DIM * DIM];             // U[k][j]
__device__ float2 g_UT[DIM * DIM];            // U^T[j][k]
__device__ __nv_bfloat16 g_Whi[DIM * DIM];    // A hi split, [n][k]
__device__ __nv_bfloat16 g_Wlo[DIM * DIM];    // A lo split, [n][k]

__device__ __forceinline__ float2 cmul(float2 a, float2 b) {
    return make_float2(a.x * b.x - a.y * b.y, a.x * b.y + a.y * b.x);
}
__device__ __forceinline__ float2 cadd(float2 a, float2 b) {
    return make_float2(a.x + b.x, a.y + b.y);
}

// ---------------------------------------------------------------------------
// Kernel 1: build U, one WARP per column, amplitudes in registers.
// amp index t = h*32 + lane. Qubit q <-> bit (6-q); q=0,1 -> h bits, q>=2 ->
// lane bits via shfl_xor. Zero block barriers in the gate loop.
// ---------------------------------------------------------------------------
__global__ void build_u_kernel(const float* __restrict__ w) {
    __shared__ float2 gm[NLAYERS * NQ][4];
    const int tid = threadIdx.x;
    const int lane = tid & 31;
    const int wid = tid >> 5;
    const int j = blockIdx.x * 4 + wid;

    if (tid < NLAYERS * NQ) {
        const float phi = w[tid * 3 + 0];
        const float th  = w[tid * 3 + 1];
        const float om  = w[tid * 3 + 2];
        float sh, ch; sincosf(0.5f * th, &sh, &ch);
        float sap, cap, sam, cam;
        sincosf(0.5f * (phi + om), &sap, &cap);
        sincosf(0.5f * (phi - om), &sam, &cam);
        gm[tid][0] = make_float2( cap * ch, -sap * ch);
        gm[tid][1] = make_float2(-cam * sh, -sam * sh);
        gm[tid][2] = make_float2( cam * sh, -sam * sh);
        gm[tid][3] = make_float2( cap * ch,  sap * ch);
    }
    __syncthreads();

    float2 a[4];
    #pragma unroll
    for (int h = 0; h < 4; h++)
        a[h] = make_float2((h * 32 + lane) == j ? 1.f : 0.f, 0.f);

    #pragma unroll
    for (int l = 0; l < NLAYERS; l++) {
        #pragma unroll
        for (int q = 0; q < NQ; q++) {
            const int g = l * NQ + q;
            const float2 u00 = gm[g][0], u01 = gm[g][1];
            const float2 u10 = gm[g][2], u11 = gm[g][3];
            const int b = 1 << (6 - q);
            if (b >= 32) {
                const int hp = b >> 5;
                #pragma unroll
                for (int h0 = 0; h0 < 4; h0++) {
                    if (!(h0 & hp)) {
                        const int h1 = h0 | hp;
                        const float2 a0 = a[h0], a1 = a[h1];
                        a[h0] = cadd(cmul(u00, a0), cmul(u01, a1));
                        a[h1] = cadd(cmul(u10, a0), cmul(u11, a1));
                    }
                }
            } else {
                #pragma unroll
                for (int h = 0; h < 4; h++) {
                    float2 p;
                    p.x = __shfl_xor_sync(0xffffffffu, a[h].x, b);
                    p.y = __shfl_xor_sync(0xffffffffu, a[h].y, b);
                    const float2 s = a[h];
                    if (lane & b) a[h] = cadd(cmul(u10, p), cmul(u11, s));
                    else          a[h] = cadd(cmul(u00, s), cmul(u01, p));
                }
            }
        }
        const int r = (l % (NQ - 1)) + 1;
        #pragma unroll
        for (int c = 0; c < NQ; c++) {
            const int t = (c + r) % NQ;
            const int cb = 1 << (6 - c);
            const int tb = 1 << (6 - t);
            if (tb >= 32) {
                const int hb = tb >> 5;
                if (cb >= 32) {
                    const int chb = cb >> 5;
                    #pragma unroll
                    for (int h0 = 0; h0 < 4; h0++)
                        if (!(h0 & hb) && (h0 & chb)) {
                            const float2 tmp = a[h0];
                            a[h0] = a[h0 | hb];
                            a[h0 | hb] = tmp;
                        }
                } else {
                    if (lane & cb) {
                        #pragma unroll
                        for (int h0 = 0; h0 < 4; h0++)
                            if (!(h0 & hb)) {
                                const float2 tmp = a[h0];
                                a[h0] = a[h0 | hb];
                                a[h0 | hb] = tmp;
                            }
                    }
                }
            } else {
                #pragma unroll
                for (int h = 0; h < 4; h++) {
                    float2 p;
                    p.x = __shfl_xor_sync(0xffffffffu, a[h].x, tb);
                    p.y = __shfl_xor_sync(0xffffffffu, a[h].y, tb);
                    const bool ctrl = (cb >= 32) ? ((h & (cb >> 5)) != 0)
                                                 : ((lane & cb) != 0);
                    if (ctrl) a[h] = p;
                }
            }
        }
    }
    #pragma unroll
    for (int h = 0; h < 4; h++) {
        const int idx = h * 32 + lane;
        g_U[idx * DIM + j] = a[h];
        g_UT[j * DIM + idx] = a[h];
    }
}

// ---------------------------------------------------------------------------
// Kernel 2: A[i][j] = sum_k d_k * Re(conj(U[k][i]) U[k][j]); bf16 hi/lo split
// ---------------------------------------------------------------------------
__global__ void build_w_kernel() {
    __shared__ float2 ui[DIM];
    const int i = blockIdx.x;
    const int j = threadIdx.x;
    ui[j] = g_UT[i * DIM + j];
    __syncthreads();
    float acc = 0.f;
    #pragma unroll 4
    for (int k = 0; k < DIM; k++) {
        const float dk = (((k >> 6) ^ k) & 1) ? -1.f : 1.f;
        const float2 uj = g_U[k * DIM + j];
        acc += dk * (ui[k].x * uj.x + ui[k].y * uj.y);
    }
    const __nv_bfloat16 h = __float2bfloat16(acc);
    const __nv_bfloat16 lo = __float2bfloat16(acc - __bfloat162float(h));
    g_Whi[i * DIM + j] = h;
    g_Wlo[i * DIM + j] = lo;
}

// ---------------------------------------------------------------------------
// Main kernel
// ---------------------------------------------------------------------------
#define SM_ZHI 0
#define SM_ZLO 34816
#define SM_WHI 69632
#define SM_WLO 104448
#define SM_XF  139264
#define SM_S   206848
#define SM_PD  207360
#define SM_TOTAL 208384

__device__ __forceinline__ void ldsm4(uint32_t& r0, uint32_t& r1, uint32_t& r2,
                                      uint32_t& r3, uint32_t addr) {
    asm volatile("ldmatrix.sync.aligned.m8n8.x4.shared.b16 {%0,%1,%2,%3}, [%4];"
                 : "=r"(r0), "=r"(r1), "=r"(r2), "=r"(r3) : "r"(addr));
}
__device__ __forceinline__ void mma16816(float* d, const uint32_t* a, const uint32_t* b) {
    asm volatile(
        "mma.sync.aligned.m16n8k16.row.col.f32.bf16.bf16.f32 "
        "{%0,%1,%2,%3}, {%4,%5,%6,%7}, {%8,%9}, {%0,%1,%2,%3};"
        : "+f"(d[0]), "+f"(d[1]), "+f"(d[2]), "+f"(d[3])
        : "r"(a[0]), "r"(a[1]), "r"(a[2]), "r"(a[3]), "r"(b[0]), "r"(b[1]));
}
__device__ __forceinline__ uint32_t pack2bf(float a, float b) {
    return ((uint32_t)__bfloat16_as_ushort(__float2bfloat16(b)) << 16) |
           (uint32_t)__bfloat16_as_ushort(__float2bfloat16(a));
}

__global__ void __launch_bounds__(NTHREADS, 1)
vqa_main_kernel(const float* __restrict__ x, float* __restrict__ out, int ntiles) {
    extern __shared__ char smem[];
    const uint32_t sbase = (uint32_t)__cvta_generic_to_shared(smem);
    float* xf   = (float*)(smem + SM_XF);
    float* sarr = (float*)(smem + SM_S);
    float* pd   = (float*)(smem + SM_PD);

    const int tid = threadIdx.x;
    const int lane = tid & 31;
    const int wid = tid >> 5;
    const int mi = wid & 3;   // m-stripe (32 rows)
    const int nh = wid >> 2;  // n-half (64 cols)

    // ---- load W (A hi/lo) into padded smem, once per CTA ----
    {
        const uint2* whi_g = (const uint2*)g_Whi;
        const uint2* wlo_g = (const uint2*)g_Wlo;
        for (int idx = tid; idx < DIM * 32; idx += NTHREADS) {
            const int i = idx >> 5, c = idx & 31;
            *(uint2*)(smem + SM_WHI + i * (KPAD * 2) + c * 8) = whi_g[idx];
            *(uint2*)(smem + SM_WLO + i * (KPAD * 2) + c * 8) = wlo_g[idx];
        }
    }

    // ldmatrix lane base addresses (bytes)
    const uint32_t abase = sbase + SM_ZHI +
        (uint32_t)(((32 * mi + (lane & 15)) * KPAD + 8 * (lane >> 4)) * 2);
    const int rowL = (lane & 7) + ((lane >> 4) & 1) * 8;
    const int kL = ((lane >> 3) & 1) * 8;
    const uint32_t bbase = sbase + SM_WHI +
        (uint32_t)(((64 * nh + rowL) * KPAD + kL) * 2);

    // ---- prologue: prefetch first tile into registers ----
    float4 v[16];
    {
        const int t0 = blockIdx.x;
        if (t0 < ntiles) {
            const float4* src = (const float4*)x + (size_t)t0 * 4096;
            #pragma unroll
            for (int i = 0; i < 16; i++)
                v[i] = src[(wid * 16 + i) * 32 + lane];
        }
    }

    for (int tile = blockIdx.x; tile < ntiles; tile += (int)gridDim.x) {
        // ---- phase 1: convert registers -> xf + bf16 hi/lo + norms ----
        #pragma unroll
        for (int rr = 0; rr < 16; rr++) {
            const int row = wid * 16 + rr;
            const float4 vv = v[rr];
            *(float4*)(xf + row * XPAD + lane * 4) = vv;
            float ss = vv.x * vv.x + vv.y * vv.y + vv.z * vv.z + vv.w * vv.w;
            #pragma unroll
            for (int o = 16; o > 0; o >>= 1) ss += __shfl_xor_sync(0xffffffffu, ss, o);
            if (lane == 0) sarr[row] = ss;
            const float hx = __bfloat162float(__float2bfloat16(vv.x));
            const float hy = __bfloat162float(__float2bfloat16(vv.y));
            const float hz = __bfloat162float(__float2bfloat16(vv.z));
            const float hw = __bfloat162float(__float2bfloat16(vv.w));
            *(uint2*)(smem + SM_ZHI + row * (KPAD * 2) + lane * 8) =
                make_uint2(pack2bf(hx, hy), pack2bf(hz, hw));
            *(uint2*)(smem + SM_ZLO + row * (KPAD * 2) + lane * 8) =
                make_uint2(pack2bf(vv.x - hx, vv.y - hy), pack2bf(vv.z - hz, vv.w - hw));
        }
        __syncthreads();

        // ---- prefetch next tile into registers (hidden under GEMM) ----
        {
            const int nxt = tile + (int)gridDim.x;
            if (nxt < ntiles) {
                const float4* src = (const float4*)x + (size_t)nxt * 4096;
                #pragma unroll
                for (int i = 0; i < 16; i++)
                    v[i] = src[(wid * 16 + i) * 32 + lane];
            }
        }

        // ---- phase 2: fused GEMM, one pass over kk ----
        float d[2][8][4];
        #pragma unroll
        for (int mt = 0; mt < 2; mt++)
            #pragma unroll
            for (int nt = 0; nt < 8; nt++)
                #pragma unroll
                for (int q = 0; q < 4; q++) d[mt][nt][q] = 0.f;

        const uint32_t ZLO_OFF = (uint32_t)(SM_ZLO - SM_ZHI);
        const uint32_t WLO_OFF = (uint32_t)(SM_WLO - SM_WHI);

        #pragma unroll
        for (int kk = 0; kk < 8; kk++) {
            const uint32_t ko = (uint32_t)(kk * 32);  // 16 elems * 2B
            uint32_t ah0[4], ah1[4], al0[4], al1[4];
            ldsm4(ah0[0], ah0[1], ah0[2], ah0[3], abase + ko);
            ldsm4(ah1[0], ah1[1], ah1[2], ah1[3], abase + ko + 16 * KPAD * 2);
            ldsm4(al0[0], al0[1], al0[2], al0[3], abase + ZLO_OFF + ko);
            ldsm4(al1[0], al1[1], al1[2], al1[3], abase + ZLO_OFF + ko + 16 * KPAD * 2);
            uint32_t bh[4][4], bl[4][4];
            #pragma unroll
            for (int ntp = 0; ntp < 4; ntp++) {
                const uint32_t bo = bbase + ko + (uint32_t)(ntp * 16 * KPAD * 2);
                ldsm4(bh[ntp][0], bh[ntp][1], bh[ntp][2], bh[ntp][3], bo);
                ldsm4(bl[ntp][0], bl[ntp][1], bl[ntp][2], bl[ntp][3], bo + WLO_OFF);
            }
            #pragma unroll
            for (int ntp = 0; ntp < 4; ntp++) {
                // xhi * Whi
                mma16816(d[0][2 * ntp + 0], ah0, &bh[ntp][0]);
                mma16816(d[0][2 * ntp + 1], ah0, &bh[ntp][2]);
                mma16816(d[1][2 * ntp + 0], ah1, &bh[ntp][0]);
                mma16816(d[1][2 * ntp + 1], ah1, &bh[ntp][2]);
                // xlo * Whi
                mma16816(d[0][2 * ntp + 0], al0, &bh[ntp][0]);
                mma16816(d[0][2 * ntp + 1], al0, &bh[ntp][2]);
                mma16816(d[1][2 * ntp + 0], al1, &bh[ntp][0]);
                mma16816(d[1][2 * ntp + 1], al1, &bh[ntp][2]);
                // xhi * Wlo
                mma16816(d[0][2 * ntp + 0], ah0, &bl[ntp][0]);
                mma16816(d[0][2 * ntp + 1], ah0, &bl[ntp][2]);
                mma16816(d[1][2 * ntp + 0], ah1, &bl[ntp][0]);
                mma16816(d[1][2 * ntp + 1], ah1, &bl[ntp][2]);
            }
        }

        // ---- phase 3: epilogue — out[m] = (y . x)/s ----
        const int tq = lane & 3;
        const int tr = lane >> 2;
        float racc[4] = {0.f, 0.f, 0.f, 0.f};
        #pragma unroll
        for (int mt = 0; mt < 2; mt++) {
            const int row0 = 32 * mi + 16 * mt + tr;
            const float* x0 = xf + row0 * XPAD;
            const float* x1 = x0 + 8 * XPAD;
            #pragma unroll
            for (int nt = 0; nt < 8; nt++) {
                const int c = 64 * nh + 8 * nt + 2 * tq;
                racc[2 * mt]     += d[mt][nt][0] * x0[c] + d[mt][nt][1] * x0[c + 1];
                racc[2 * mt + 1] += d[mt][nt][2] * x1[c] + d[mt][nt][3] * x1[c + 1];
            }
        }
        #pragma unroll
        for (int q = 0; q < 4; q++) {
            racc[q] += __shfl_xor_sync(0xffffffffu, racc[q], 1);
            racc[q] += __shfl_xor_sync(0xffffffffu, racc[q], 2);
        }
        if (tq == 0) {
            #pragma unroll
            for (int q = 0; q < 4; q++) {
                const int row = 32 * mi + 8 * q + tr;
                pd[row * 2 + nh] = racc[q];
            }
        }
        __syncthreads();
        if (tid < TILE_M) {
            out[(size_t)tile * TILE_M + tid] =
                (pd[tid * 2] + pd[tid * 2 + 1]) / sarr[tid];
        }
        __syncthreads();
    }
}

// ---------------------------------------------------------------------------
extern "C" void kernel_launch(void* const* d_in, const int* in_sizes, int n_in,
                              void* d_out, int out_size) {
    const float* x = (const float*)d_in[0];
    const float* w = (const float*)d_in[1];
    float* out = (float*)d_out;

    cudaFuncSetAttribute(vqa_main_kernel,
                         cudaFuncAttributeMaxDynamicSharedMemorySize, SM_TOTAL);

    build_u_kernel<<<DIM / 4, 128>>>(w);
    build_w_kernel<<<DIM, DIM>>>();

    const int rows = in_sizes[0] / DIM;
    const int ntiles = rows / TILE_M;
    vqa_main_kernel<<<152, NTHREADS, SM_TOTAL>>>(x, out, ntiles);
}

// round 10
// speedup vs baseline: 1.6727x; 1.0631x over previous
#include <cuda_runtime.h>
#include <cuda_bf16.h>
#include <cstdint>

#define DIM 128
#define NLAYERS 4
#define NQ 7
#define TILE_M 64
#define NTHREADS 256
#define KPAD 136      // bf16 elems per smem row (conflict-free ldmatrix)

// ---- device globals ----
__device__ float2 g_U[DIM * DIM];             // U[k][j]
__device__ float2 g_UT[DIM * DIM];            // U^T[j][k]
__device__ __nv_bfloat16 g_Whi[DIM * DIM];    // A hi split, [n][k]
__device__ __nv_bfloat16 g_Wlo[DIM * DIM];    // A lo split, [n][k]

__device__ __forceinline__ float2 cmul(float2 a, float2 b) {
    return make_float2(a.x * b.x - a.y * b.y, a.x * b.y + a.y * b.x);
}
__device__ __forceinline__ float2 cadd(float2 a, float2 b) {
    return make_float2(a.x + b.x, a.y + b.y);
}

// ---------------------------------------------------------------------------
// Kernel 1: build U, one WARP per column, amplitudes in registers.
// ---------------------------------------------------------------------------
__global__ void build_u_kernel(const float* __restrict__ w) {
    __shared__ float2 gm[NLAYERS * NQ][4];
    const int tid = threadIdx.x;
    const int lane = tid & 31;
    const int wid = tid >> 5;
    const int j = blockIdx.x * 4 + wid;

    if (tid < NLAYERS * NQ) {
        const float phi = w[tid * 3 + 0];
        const float th  = w[tid * 3 + 1];
        const float om  = w[tid * 3 + 2];
        float sh, ch; sincosf(0.5f * th, &sh, &ch);
        float sap, cap, sam, cam;
        sincosf(0.5f * (phi + om), &sap, &cap);
        sincosf(0.5f * (phi - om), &sam, &cam);
        gm[tid][0] = make_float2( cap * ch, -sap * ch);
        gm[tid][1] = make_float2(-cam * sh, -sam * sh);
        gm[tid][2] = make_float2( cam * sh, -sam * sh);
        gm[tid][3] = make_float2( cap * ch,  sap * ch);
    }
    __syncthreads();

    float2 a[4];
    #pragma unroll
    for (int h = 0; h < 4; h++)
        a[h] = make_float2((h * 32 + lane) == j ? 1.f : 0.f, 0.f);

    #pragma unroll
    for (int l = 0; l < NLAYERS; l++) {
        #pragma unroll
        for (int q = 0; q < NQ; q++) {
            const int g = l * NQ + q;
            const float2 u00 = gm[g][0], u01 = gm[g][1];
            const float2 u10 = gm[g][2], u11 = gm[g][3];
            const int b = 1 << (6 - q);
            if (b >= 32) {
                const int hp = b >> 5;
                #pragma unroll
                for (int h0 = 0; h0 < 4; h0++) {
                    if (!(h0 & hp)) {
                        const int h1 = h0 | hp;
                        const float2 a0 = a[h0], a1 = a[h1];
                        a[h0] = cadd(cmul(u00, a0), cmul(u01, a1));
                        a[h1] = cadd(cmul(u10, a0), cmul(u11, a1));
                    }
                }
            } else {
                #pragma unroll
                for (int h = 0; h < 4; h++) {
                    float2 p;
                    p.x = __shfl_xor_sync(0xffffffffu, a[h].x, b);
                    p.y = __shfl_xor_sync(0xffffffffu, a[h].y, b);
                    const float2 s = a[h];
                    if (lane & b) a[h] = cadd(cmul(u10, p), cmul(u11, s));
                    else          a[h] = cadd(cmul(u00, s), cmul(u01, p));
                }
            }
        }
        const int r = (l % (NQ - 1)) + 1;
        #pragma unroll
        for (int c = 0; c < NQ; c++) {
            const int t = (c + r) % NQ;
            const int cb = 1 << (6 - c);
            const int tb = 1 << (6 - t);
            if (tb >= 32) {
                const int hb = tb >> 5;
                if (cb >= 32) {
                    const int chb = cb >> 5;
                    #pragma unroll
                    for (int h0 = 0; h0 < 4; h0++)
                        if (!(h0 & hb) && (h0 & chb)) {
                            const float2 tmp = a[h0];
                            a[h0] = a[h0 | hb];
                            a[h0 | hb] = tmp;
                        }
                } else {
                    if (lane & cb) {
                        #pragma unroll
                        for (int h0 = 0; h0 < 4; h0++)
                            if (!(h0 & hb)) {
                                const float2 tmp = a[h0];
                                a[h0] = a[h0 | hb];
                                a[h0 | hb] = tmp;
                            }
                    }
                }
            } else {
                #pragma unroll
                for (int h = 0; h < 4; h++) {
                    float2 p;
                    p.x = __shfl_xor_sync(0xffffffffu, a[h].x, tb);
                    p.y = __shfl_xor_sync(0xffffffffu, a[h].y, tb);
                    const bool ctrl = (cb >= 32) ? ((h & (cb >> 5)) != 0)
                                                 : ((lane & cb) != 0);
                    if (ctrl) a[h] = p;
                }
            }
        }
    }
    #pragma unroll
    for (int h = 0; h < 4; h++) {
        const int idx = h * 32 + lane;
        g_U[idx * DIM + j] = a[h];
        g_UT[j * DIM + idx] = a[h];
    }
}

// ---------------------------------------------------------------------------
// Kernel 2: A[i][j] = sum_k d_k * Re(conj(U[k][i]) U[k][j]); bf16 hi/lo split
// ---------------------------------------------------------------------------
__global__ void build_w_kernel() {
    __shared__ float2 ui[DIM];
    const int i = blockIdx.x;
    const int j = threadIdx.x;
    ui[j] = g_UT[i * DIM + j];
    __syncthreads();
    float acc = 0.f;
    #pragma unroll 4
    for (int k = 0; k < DIM; k++) {
        const float dk = (((k >> 6) ^ k) & 1) ? -1.f : 1.f;
        const float2 uj = g_U[k * DIM + j];
        acc += dk * (ui[k].x * uj.x + ui[k].y * uj.y);
    }
    const __nv_bfloat16 h = __float2bfloat16(acc);
    const __nv_bfloat16 lo = __float2bfloat16(acc - __bfloat162float(h));
    g_Whi[i * DIM + j] = h;
    g_Wlo[i * DIM + j] = lo;
}

// ---------------------------------------------------------------------------
// Main kernel: TILE_M=64, occupancy 2 (phase overlap across co-resident CTAs)
// ---------------------------------------------------------------------------
#define SM_ZHI 0
#define SM_ZLO 17408
#define SM_WHI 34816
#define SM_WLO 69632
#define SM_PD  104448
#define SM_PS  105472
#define SM_TOTAL 106496

__device__ __forceinline__ void ldsm4(uint32_t& r0, uint32_t& r1, uint32_t& r2,
                                      uint32_t& r3, uint32_t addr) {
    asm volatile("ldmatrix.sync.aligned.m8n8.x4.shared.b16 {%0,%1,%2,%3}, [%4];"
                 : "=r"(r0), "=r"(r1), "=r"(r2), "=r"(r3) : "r"(addr));
}
__device__ __forceinline__ void mma16816(float* d, const uint32_t* a, const uint32_t* b) {
    asm volatile(
        "mma.sync.aligned.m16n8k16.row.col.f32.bf16.bf16.f32 "
        "{%0,%1,%2,%3}, {%4,%5,%6,%7}, {%8,%9}, {%0,%1,%2,%3};"
        : "+f"(d[0]), "+f"(d[1]), "+f"(d[2]), "+f"(d[3])
        : "r"(a[0]), "r"(a[1]), "r"(a[2]), "r"(a[3]), "r"(b[0]), "r"(b[1]));
}
__device__ __forceinline__ uint32_t pack2bf(float a, float b) {
    return ((uint32_t)__bfloat16_as_ushort(__float2bfloat16(b)) << 16) |
           (uint32_t)__bfloat16_as_ushort(__float2bfloat16(a));
}

__global__ void __launch_bounds__(NTHREADS, 2)
vqa_main_kernel(const float* __restrict__ x, float* __restrict__ out, int ntiles) {
    extern __shared__ char smem[];
    const uint32_t sbase = (uint32_t)__cvta_generic_to_shared(smem);
    float* pd = (float*)(smem + SM_PD);
    float* ps = (float*)(smem + SM_PS);

    const int tid = threadIdx.x;
    const int lane = tid & 31;
    const int wid = tid >> 5;
    const int mi = wid & 1;   // m-stripe (32 rows)
    const int nh = wid >> 1;  // n-quarter (32 cols)

    // ---- load W (A hi/lo) into padded smem, once per CTA ----
    {
        const uint2* whi_g = (const uint2*)g_Whi;
        const uint2* wlo_g = (const uint2*)g_Wlo;
        for (int idx = tid; idx < DIM * 32; idx += NTHREADS) {
            const int i = idx >> 5, c = idx & 31;
            *(uint2*)(smem + SM_WHI + i * (KPAD * 2) + c * 8) = whi_g[idx];
            *(uint2*)(smem + SM_WLO + i * (KPAD * 2) + c * 8) = wlo_g[idx];
        }
    }

    // ldmatrix lane base addresses (bytes)
    const uint32_t abase = sbase + SM_ZHI +
        (uint32_t)(((32 * mi + (lane & 15)) * KPAD + 8 * (lane >> 4)) * 2);
    const int rowL = (lane & 7) + ((lane >> 4) & 1) * 8;
    const int kL = ((lane >> 3) & 1) * 8;
    const uint32_t bbase = sbase + SM_WHI +
        (uint32_t)(((32 * nh + rowL) * KPAD + kL) * 2);

    const uint32_t ZLO_OFF = (uint32_t)(SM_ZLO - SM_ZHI);
    const uint32_t WLO_OFF = (uint32_t)(SM_WLO - SM_WHI);

    for (int tile = blockIdx.x; tile < ntiles; tile += (int)gridDim.x) {
        // ---- phase 1: load + convert (no reductions, pure streaming) ----
        const float4* xt = (const float4*)x + (size_t)tile * (TILE_M * 32);
        #pragma unroll
        for (int rr = 0; rr < 8; rr++) {
            const int row = wid * 8 + rr;
            const float4 vv = xt[row * 32 + lane];
            const float hx = __bfloat162float(__float2bfloat16(vv.x));
            const float hy = __bfloat162float(__float2bfloat16(vv.y));
            const float hz = __bfloat162float(__float2bfloat16(vv.z));
            const float hw = __bfloat162float(__float2bfloat16(vv.w));
            *(uint2*)(smem + SM_ZHI + row * (KPAD * 2) + lane * 8) =
                make_uint2(pack2bf(hx, hy), pack2bf(hz, hw));
            *(uint2*)(smem + SM_ZLO + row * (KPAD * 2) + lane * 8) =
                make_uint2(pack2bf(vv.x - hx, vv.y - hy), pack2bf(vv.z - hz, vv.w - hw));
        }
        __syncthreads();

        // ---- phase 2: fused GEMM (3 precision segments in one kk pass) ----
        float d[2][4][4];
        #pragma unroll
        for (int mt = 0; mt < 2; mt++)
            #pragma unroll
            for (int nt = 0; nt < 4; nt++)
                #pragma unroll
                for (int q = 0; q < 4; q++) d[mt][nt][q] = 0.f;

        #pragma unroll
        for (int kk = 0; kk < 8; kk++) {
            const uint32_t ko = (uint32_t)(kk * 32);  // 16 elems * 2B
            uint32_t ah0[4], ah1[4], al0[4], al1[4];
            ldsm4(ah0[0], ah0[1], ah0[2], ah0[3], abase + ko);
            ldsm4(ah1[0], ah1[1], ah1[2], ah1[3], abase + ko + 16 * KPAD * 2);
            ldsm4(al0[0], al0[1], al0[2], al0[3], abase + ZLO_OFF + ko);
            ldsm4(al1[0], al1[1], al1[2], al1[3], abase + ZLO_OFF + ko + 16 * KPAD * 2);
            uint32_t bh[2][4], bl[2][4];
            #pragma unroll
            for (int ntp = 0; ntp < 2; ntp++) {
                const uint32_t bo = bbase + ko + (uint32_t)(ntp * 16 * KPAD * 2);
                ldsm4(bh[ntp][0], bh[ntp][1], bh[ntp][2], bh[ntp][3], bo);
                ldsm4(bl[ntp][0], bl[ntp][1], bl[ntp][2], bl[ntp][3], bo + WLO_OFF);
            }
            #pragma unroll
            for (int ntp = 0; ntp < 2; ntp++) {
                mma16816(d[0][2 * ntp + 0], ah0, &bh[ntp][0]);
                mma16816(d[0][2 * ntp + 1], ah0, &bh[ntp][2]);
                mma16816(d[1][2 * ntp + 0], ah1, &bh[ntp][0]);
                mma16816(d[1][2 * ntp + 1], ah1, &bh[ntp][2]);

                mma16816(d[0][2 * ntp + 0], al0, &bh[ntp][0]);
                mma16816(d[0][2 * ntp + 1], al0, &bh[ntp][2]);
                mma16816(d[1][2 * ntp + 0], al1, &bh[ntp][0]);
                mma16816(d[1][2 * ntp + 1], al1, &bh[ntp][2]);

                mma16816(d[0][2 * ntp + 0], ah0, &bl[ntp][0]);
                mma16816(d[0][2 * ntp + 1], ah0, &bl[ntp][2]);
                mma16816(d[1][2 * ntp + 0], ah1, &bl[ntp][0]);
                mma16816(d[1][2 * ntp + 1], ah1, &bl[ntp][2]);
            }
        }

        // ---- phase 3: epilogue — out[m] = (y.x)/(x.x), x = hi+lo ----
        const int tq = lane & 3;
        const int tr = lane >> 2;
        float racc[4] = {0.f, 0.f, 0.f, 0.f};
        float sacc[4] = {0.f, 0.f, 0.f, 0.f};
        #pragma unroll
        for (int mt = 0; mt < 2; mt++) {
            const int row0 = 32 * mi + 16 * mt + tr;
            #pragma unroll
            for (int nt = 0; nt < 4; nt++) {
                const int c = 32 * nh + 8 * nt + 2 * tq;
                const int o0 = (row0 * KPAD + c) * 2;
                const int o1 = ((row0 + 8) * KPAD + c) * 2;
                const float2 h0 = __bfloat1622float2(*(__nv_bfloat162*)(smem + SM_ZHI + o0));
                const float2 l0 = __bfloat1622float2(*(__nv_bfloat162*)(smem + SM_ZLO + o0));
                const float2 h1 = __bfloat1622float2(*(__nv_bfloat162*)(smem + SM_ZHI + o1));
                const float2 l1 = __bfloat1622float2(*(__nv_bfloat162*)(smem + SM_ZLO + o1));
                const float x0a = h0.x + l0.x, x0b = h0.y + l0.y;
                const float x1a = h1.x + l1.x, x1b = h1.y + l1.y;
                racc[2 * mt]     += d[mt][nt][0] * x0a + d[mt][nt][1] * x0b;
                racc[2 * mt + 1] += d[mt][nt][2] * x1a + d[mt][nt][3] * x1b;
                sacc[2 * mt]     += x0a * x0a + x0b * x0b;
                sacc[2 * mt + 1] += x1a * x1a + x1b * x1b;
            }
        }
        #pragma unroll
        for (int q = 0; q < 4; q++) {
            racc[q] += __shfl_xor_sync(0xffffffffu, racc[q], 1);
            racc[q] += __shfl_xor_sync(0xffffffffu, racc[q], 2);
            sacc[q] += __shfl_xor_sync(0xffffffffu, sacc[q], 1);
            sacc[q] += __shfl_xor_sync(0xffffffffu, sacc[q], 2);
        }
        if (tq == 0) {
            #pragma unroll
            for (int q = 0; q < 4; q++) {
                const int row = 32 * mi + 8 * q + tr;
                pd[row * 4 + nh] = racc[q];
                ps[row * 4 + nh] = sacc[q];
            }
        }
        __syncthreads();
        if (tid < TILE_M) {
            const float num = pd[tid * 4] + pd[tid * 4 + 1] +
                              pd[tid * 4 + 2] + pd[tid * 4 + 3];
            const float den = ps[tid * 4] + ps[tid * 4 + 1] +
                              ps[tid * 4 + 2] + ps[tid * 4 + 3];
            out[(size_t)tile * TILE_M + tid] = num / den;
        }
        __syncthreads();
    }
}

// ---------------------------------------------------------------------------
extern "C" void kernel_launch(void* const* d_in, const int* in_sizes, int n_in,
                              void* d_out, int out_size) {
    const float* x = (const float*)d_in[0];
    const float* w = (const float*)d_in[1];
    float* out = (float*)d_out;

    cudaFuncSetAttribute(vqa_main_kernel,
                         cudaFuncAttributeMaxDynamicSharedMemorySize, SM_TOTAL);
    cudaFuncSetAttribute(vqa_main_kernel,
                         cudaFuncAttributePreferredSharedMemoryCarveout, 100);

    build_u_kernel<<<DIM / 4, 128>>>(w);
    build_w_kernel<<<DIM, DIM>>>();

    const int rows = in_sizes[0] / DIM;
    const int ntiles = rows / TILE_M;
    vqa_main_kernel<<<304, NTHREADS, SM_TOTAL>>>(x, out, ntiles);
}

// round 13
// speedup vs baseline: 2.2336x; 1.3353x over previous
#include <cuda_runtime.h>
#include <cuda_fp16.h>
#include <cstdint>

#define DIM 128
#define NLAYERS 4
#define NQ 7
#define TILE_M 64
#define NTHREADS 256
#define KPAD 136      // fp16 elems per smem row (conflict-free ldmatrix)

// ---- device globals ----
__device__ float2 g_U[DIM * DIM];    // U[k][j]
__device__ float2 g_UT[DIM * DIM];   // U^T[j][k]
__device__ __half g_W[DIM * DIM];    // A in fp16, [n][k]

__device__ __forceinline__ float2 cmul(float2 a, float2 b) {
    return make_float2(a.x * b.x - a.y * b.y, a.x * b.y + a.y * b.x);
}
__device__ __forceinline__ float2 cadd(float2 a, float2 b) {
    return make_float2(a.x + b.x, a.y + b.y);
}

// ---------------------------------------------------------------------------
// Kernel 1: build U, one WARP per column, amplitudes in registers.
// ---------------------------------------------------------------------------
__global__ void build_u_kernel(const float* __restrict__ w) {
    __shared__ float2 gm[NLAYERS * NQ][4];
    const int tid = threadIdx.x;
    const int lane = tid & 31;
    const int wid = tid >> 5;
    const int j = blockIdx.x * 4 + wid;

    if (tid < NLAYERS * NQ) {
        const float phi = w[tid * 3 + 0];
        const float th  = w[tid * 3 + 1];
        const float om  = w[tid * 3 + 2];
        float sh, ch; sincosf(0.5f * th, &sh, &ch);
        float sap, cap, sam, cam;
        sincosf(0.5f * (phi + om), &sap, &cap);
        sincosf(0.5f * (phi - om), &sam, &cam);
        gm[tid][0] = make_float2( cap * ch, -sap * ch);
        gm[tid][1] = make_float2(-cam * sh, -sam * sh);
        gm[tid][2] = make_float2( cam * sh, -sam * sh);
        gm[tid][3] = make_float2( cap * ch,  sap * ch);
    }
    __syncthreads();

    float2 a[4];
    #pragma unroll
    for (int h = 0; h < 4; h++)
        a[h] = make_float2((h * 32 + lane) == j ? 1.f : 0.f, 0.f);

    #pragma unroll
    for (int l = 0; l < NLAYERS; l++) {
        #pragma unroll
        for (int q = 0; q < NQ; q++) {
            const int g = l * NQ + q;
            const float2 u00 = gm[g][0], u01 = gm[g][1];
            const float2 u10 = gm[g][2], u11 = gm[g][3];
            const int b = 1 << (6 - q);
            if (b >= 32) {
                const int hp = b >> 5;
                #pragma unroll
                for (int h0 = 0; h0 < 4; h0++) {
                    if (!(h0 & hp)) {
                        const int h1 = h0 | hp;
                        const float2 a0 = a[h0], a1 = a[h1];
                        a[h0] = cadd(cmul(u00, a0), cmul(u01, a1));
                        a[h1] = cadd(cmul(u10, a0), cmul(u11, a1));
                    }
                }
            } else {
                #pragma unroll
                for (int h = 0; h < 4; h++) {
                    float2 p;
                    p.x = __shfl_xor_sync(0xffffffffu, a[h].x, b);
                    p.y = __shfl_xor_sync(0xffffffffu, a[h].y, b);
                    const float2 s = a[h];
                    if (lane & b) a[h] = cadd(cmul(u10, p), cmul(u11, s));
                    else          a[h] = cadd(cmul(u00, s), cmul(u01, p));
                }
            }
        }
        const int r = (l % (NQ - 1)) + 1;
        #pragma unroll
        for (int c = 0; c < NQ; c++) {
            const int t = (c + r) % NQ;
            const int cb = 1 << (6 - c);
            const int tb = 1 << (6 - t);
            if (tb >= 32) {
                const int hb = tb >> 5;
                if (cb >= 32) {
                    const int chb = cb >> 5;
                    #pragma unroll
                    for (int h0 = 0; h0 < 4; h0++)
                        if (!(h0 & hb) && (h0 & chb)) {
                            const float2 tmp = a[h0];
                            a[h0] = a[h0 | hb];
                            a[h0 | hb] = tmp;
                        }
                } else {
                    if (lane & cb) {
                        #pragma unroll
                        for (int h0 = 0; h0 < 4; h0++)
                            if (!(h0 & hb)) {
                                const float2 tmp = a[h0];
                                a[h0] = a[h0 | hb];
                                a[h0 | hb] = tmp;
                            }
                    }
                }
            } else {
                #pragma unroll
                for (int h = 0; h < 4; h++) {
                    float2 p;
                    p.x = __shfl_xor_sync(0xffffffffu, a[h].x, tb);
                    p.y = __shfl_xor_sync(0xffffffffu, a[h].y, tb);
                    const bool ctrl = (cb >= 32) ? ((h & (cb >> 5)) != 0)
                                                 : ((lane & cb) != 0);
                    if (ctrl) a[h] = p;
                }
            }
        }
    }
    #pragma unroll
    for (int h = 0; h < 4; h++) {
        const int idx = h * 32 + lane;
        g_U[idx * DIM + j] = a[h];
        g_UT[j * DIM + idx] = a[h];
    }
}

// ---------------------------------------------------------------------------
// Kernel 2: A[i][j] = sum_k d_k * Re(conj(U[k][i]) U[k][j]); fp16
// ---------------------------------------------------------------------------
__global__ void build_w_kernel() {
    __shared__ float2 ui[DIM];
    const int i = blockIdx.x;
    const int j = threadIdx.x;
    ui[j] = g_UT[i * DIM + j];
    __syncthreads();
    float acc = 0.f;
    #pragma unroll 4
    for (int k = 0; k < DIM; k++) {
        const float dk = (((k >> 6) ^ k) & 1) ? -1.f : 1.f;
        const float2 uj = g_U[k * DIM + j];
        acc += dk * (ui[k].x * uj.x + ui[k].y * uj.y);
    }
    g_W[i * DIM + j] = __float2half_rn(acc);
}

// ---------------------------------------------------------------------------
// Main kernel: fp16, 2 precision segments (A*xhi + A*xlo), TILE_M=64
// ---------------------------------------------------------------------------
#define SM_ZHI 0
#define SM_ZLO 17408
#define SM_W   34816
#define SM_PD  69632
#define SM_PS  70656
#define SM_TOTAL 71680

__device__ __forceinline__ void ldsm4(uint32_t& r0, uint32_t& r1, uint32_t& r2,
                                      uint32_t& r3, uint32_t addr) {
    asm volatile("ldmatrix.sync.aligned.m8n8.x4.shared.b16 {%0,%1,%2,%3}, [%4];"
                 : "=r"(r0), "=r"(r1), "=r"(r2), "=r"(r3) : "r"(addr));
}
__device__ __forceinline__ void mma16816(float* d, const uint32_t* a, const uint32_t* b) {
    asm volatile(
        "mma.sync.aligned.m16n8k16.row.col.f32.f16.f16.f32 "
        "{%0,%1,%2,%3}, {%4,%5,%6,%7}, {%8,%9}, {%0,%1,%2,%3};"
        : "+f"(d[0]), "+f"(d[1]), "+f"(d[2]), "+f"(d[3])
        : "r"(a[0]), "r"(a[1]), "r"(a[2]), "r"(a[3]), "r"(b[0]), "r"(b[1]));
}
__device__ __forceinline__ uint32_t pack2h(float a, float b) {
    const __half2 h = __floats2half2_rn(a, b);
    return *(const uint32_t*)&h;
}

__global__ void __launch_bounds__(NTHREADS, 2)
vqa_main_kernel(const float* __restrict__ x, float* __restrict__ out, int ntiles) {
    extern __shared__ char smem[];
    const uint32_t sbase = (uint32_t)__cvta_generic_to_shared(smem);
    float* pd = (float*)(smem + SM_PD);
    float* ps = (float*)(smem + SM_PS);

    const int tid = threadIdx.x;
    const int lane = tid & 31;
    const int wid = tid >> 5;
    const int mi = wid & 1;   // m-stripe (32 rows)
    const int nh = wid >> 1;  // n-quarter (32 cols)

    // ---- load W (fp16 A) into padded smem, once per CTA ----
    {
        const uint2* w_g = (const uint2*)g_W;
        for (int idx = tid; idx < DIM * 32; idx += NTHREADS) {
            const int i = idx >> 5, c = idx & 31;
            *(uint2*)(smem + SM_W + i * (KPAD * 2) + c * 8) = w_g[idx];
        }
    }

    // ldmatrix lane base addresses (bytes)
    const uint32_t abase = sbase + SM_ZHI +
        (uint32_t)(((32 * mi + (lane & 15)) * KPAD + 8 * (lane >> 4)) * 2);
    const int rowL = (lane & 7) + ((lane >> 4) & 1) * 8;
    const int kL = ((lane >> 3) & 1) * 8;
    const uint32_t bbase = sbase + SM_W +
        (uint32_t)(((32 * nh + rowL) * KPAD + kL) * 2);

    const uint32_t ZLO_OFF = (uint32_t)(SM_ZLO - SM_ZHI);

    for (int tile = blockIdx.x; tile < ntiles; tile += (int)gridDim.x) {
        // ---- phase 1: load + convert (pure streaming) ----
        const float4* xt = (const float4*)x + (size_t)tile * (TILE_M * 32);
        #pragma unroll
        for (int rr = 0; rr < 8; rr++) {
            const int row = wid * 8 + rr;
            const float4 vv = xt[row * 32 + lane];
            const float hx = __half2float(__float2half_rn(vv.x));
            const float hy = __half2float(__float2half_rn(vv.y));
            const float hz = __half2float(__float2half_rn(vv.z));
            const float hw = __half2float(__float2half_rn(vv.w));
            *(uint2*)(smem + SM_ZHI + row * (KPAD * 2) + lane * 8) =
                make_uint2(pack2h(hx, hy), pack2h(hz, hw));
            *(uint2*)(smem + SM_ZLO + row * (KPAD * 2) + lane * 8) =
                make_uint2(pack2h(vv.x - hx, vv.y - hy), pack2h(vv.z - hz, vv.w - hw));
        }
        __syncthreads();

        // ---- phase 2: GEMM, 2 precision segments fused over kk ----
        float d[2][4][4];
        #pragma unroll
        for (int mt = 0; mt < 2; mt++)
            #pragma unroll
            for (int nt = 0; nt < 4; nt++)
                #pragma unroll
                for (int q = 0; q < 4; q++) d[mt][nt][q] = 0.f;

        #pragma unroll
        for (int kk = 0; kk < 8; kk++) {
            const uint32_t ko = (uint32_t)(kk * 32);  // 16 elems * 2B
            uint32_t ah0[4], ah1[4], al0[4], al1[4];
            ldsm4(ah0[0], ah0[1], ah0[2], ah0[3], abase + ko);
            ldsm4(ah1[0], ah1[1], ah1[2], ah1[3], abase + ko + 16 * KPAD * 2);
            ldsm4(al0[0], al0[1], al0[2], al0[3], abase + ZLO_OFF + ko);
            ldsm4(al1[0], al1[1], al1[2], al1[3], abase + ZLO_OFF + ko + 16 * KPAD * 2);
            uint32_t bh[2][4];
            #pragma unroll
            for (int ntp = 0; ntp < 2; ntp++) {
                const uint32_t bo = bbase + ko + (uint32_t)(ntp * 16 * KPAD * 2);
                ldsm4(bh[ntp][0], bh[ntp][1], bh[ntp][2], bh[ntp][3], bo);
            }
            #pragma unroll
            for (int ntp = 0; ntp < 2; ntp++) {
                mma16816(d[0][2 * ntp + 0], ah0, &bh[ntp][0]);
                mma16816(d[0][2 * ntp + 1], ah0, &bh[ntp][2]);
                mma16816(d[1][2 * ntp + 0], ah1, &bh[ntp][0]);
                mma16816(d[1][2 * ntp + 1], ah1, &bh[ntp][2]);

                mma16816(d[0][2 * ntp + 0], al0, &bh[ntp][0]);
                mma16816(d[0][2 * ntp + 1], al0, &bh[ntp][2]);
                mma16816(d[1][2 * ntp + 0], al1, &bh[ntp][0]);
                mma16816(d[1][2 * ntp + 1], al1, &bh[ntp][2]);
            }
        }

        // ---- phase 3: epilogue — out[m] = (y.x)/(x.x), x = hi+lo ----
        const int tq = lane & 3;
        const int tr = lane >> 2;
        float racc[4] = {0.f, 0.f, 0.f, 0.f};
        float sacc[4] = {0.f, 0.f, 0.f, 0.f};
        #pragma unroll
        for (int mt = 0; mt < 2; mt++) {
            const int row0 = 32 * mi + 16 * mt + tr;
            #pragma unroll
            for (int nt = 0; nt < 4; nt++) {
                const int c = 32 * nh + 8 * nt + 2 * tq;
                const int o0 = (row0 * KPAD + c) * 2;
                const int o1 = ((row0 + 8) * KPAD + c) * 2;
                const float2 h0 = __half22float2(*(__half2*)(smem + SM_ZHI + o0));
                const float2 l0 = __half22float2(*(__half2*)(smem + SM_ZLO + o0));
                const float2 h1 = __half22float2(*(__half2*)(smem + SM_ZHI + o1));
                const float2 l1 = __half22float2(*(__half2*)(smem + SM_ZLO + o1));
                const float x0a = h0.x + l0.x, x0b = h0.y + l0.y;
                const float x1a = h1.x + l1.x, x1b = h1.y + l1.y;
                racc[2 * mt]     += d[mt][nt][0] * x0a + d[mt][nt][1] * x0b;
                racc[2 * mt + 1] += d[mt][nt][2] * x1a + d[mt][nt][3] * x1b;
                sacc[2 * mt]     += x0a * x0a + x0b * x0b;
                sacc[2 * mt + 1] += x1a * x1a + x1b * x1b;
            }
        }
        #pragma unroll
        for (int q = 0; q < 4; q++) {
            racc[q] += __shfl_xor_sync(0xffffffffu, racc[q], 1);
            racc[q] += __shfl_xor_sync(0xffffffffu, racc[q], 2);
            sacc[q] += __shfl_xor_sync(0xffffffffu, sacc[q], 1);
            sacc[q] += __shfl_xor_sync(0xffffffffu, sacc[q], 2);
        }
        if (tq == 0) {
            #pragma unroll
            for (int q = 0; q < 4; q++) {
                const int row = 32 * mi + 8 * q + tr;
                pd[row * 4 + nh] = racc[q];
                ps[row * 4 + nh] = sacc[q];
            }
        }
        __syncthreads();
        if (tid < TILE_M) {
            const float num = pd[tid * 4] + pd[tid * 4 + 1] +
                              pd[tid * 4 + 2] + pd[tid * 4 + 3];
            const float den = ps[tid * 4] + ps[tid * 4 + 1] +
                              ps[tid * 4 + 2] + ps[tid * 4 + 3];
            out[(size_t)tile * TILE_M + tid] = num / den;
        }
        __syncthreads();
    }
}

// ---------------------------------------------------------------------------
extern "C" void kernel_launch(void* const* d_in, const int* in_sizes, int n_in,
                              void* d_out, int out_size) {
    const float* x = (const float*)d_in[0];
    const float* w = (const float*)d_in[1];
    float* out = (float*)d_out;

    cudaFuncSetAttribute(vqa_main_kernel,
                         cudaFuncAttributeMaxDynamicSharedMemorySize, SM_TOTAL);
    cudaFuncSetAttribute(vqa_main_kernel,
                         cudaFuncAttributePreferredSharedMemoryCarveout, 100);

    build_u_kernel<<<DIM / 4, 128>>>(w);
    build_w_kernel<<<DIM, DIM>>>();

    const int rows = in_sizes[0] / DIM;
    const int ntiles = rows / TILE_M;
    vqa_main_kernel<<<304, NTHREADS, SM_TOTAL>>>(x, out, ntiles);
}

// round 14
// speedup vs baseline: 2.5037x; 1.1209x over previous
#include <cuda_runtime.h>
#include <cuda_fp16.h>
#include <cstdint>

#define DIM 128
#define NLAYERS 4
#define NQ 7
#define TILE_M 64
#define NTHREADS 256
#define KPAD 136      // fp16 elems per smem row (conflict-free ldmatrix)

// ---- device globals ----
__device__ float2 g_U[DIM * DIM];    // U[k][j]
__device__ float2 g_UT[DIM * DIM];   // U^T[j][k]
__device__ __half g_W[DIM * DIM];    // A in fp16, [n][k] (symmetric)
__device__ int g_ctr;                // dynamic tile counter

__device__ __forceinline__ float2 cmul(float2 a, float2 b) {
    return make_float2(a.x * b.x - a.y * b.y, a.x * b.y + a.y * b.x);
}
__device__ __forceinline__ float2 cadd(float2 a, float2 b) {
    return make_float2(a.x + b.x, a.y + b.y);
}

// ---------------------------------------------------------------------------
// Kernel 1: build U, one WARP per column, amplitudes in registers.
// Layer loop NOT unrolled (I$ footprint); gate loops inside are.
// ---------------------------------------------------------------------------
__global__ void build_u_kernel(const float* __restrict__ w) {
    __shared__ float2 gm[NLAYERS * NQ][4];
    const int tid = threadIdx.x;
    const int lane = tid & 31;
    const int wid = tid >> 5;
    const int j = blockIdx.x * 4 + wid;

    if (tid < NLAYERS * NQ) {
        const float phi = w[tid * 3 + 0];
        const float th  = w[tid * 3 + 1];
        const float om  = w[tid * 3 + 2];
        float sh, ch; sincosf(0.5f * th, &sh, &ch);
        float sap, cap, sam, cam;
        sincosf(0.5f * (phi + om), &sap, &cap);
        sincosf(0.5f * (phi - om), &sam, &cam);
        gm[tid][0] = make_float2( cap * ch, -sap * ch);
        gm[tid][1] = make_float2(-cam * sh, -sam * sh);
        gm[tid][2] = make_float2( cam * sh, -sam * sh);
        gm[tid][3] = make_float2( cap * ch,  sap * ch);
    }
    __syncthreads();

    float2 a[4];
    #pragma unroll
    for (int h = 0; h < 4; h++)
        a[h] = make_float2((h * 32 + lane) == j ? 1.f : 0.f, 0.f);

    #pragma unroll 1
    for (int l = 0; l < NLAYERS; l++) {
        #pragma unroll
        for (int q = 0; q < NQ; q++) {
            const int g = l * NQ + q;
            const float2 u00 = gm[g][0], u01 = gm[g][1];
            const float2 u10 = gm[g][2], u11 = gm[g][3];
            const int b = 1 << (6 - q);
            if (b >= 32) {
                const int hp = b >> 5;
                #pragma unroll
                for (int h0 = 0; h0 < 4; h0++) {
                    if (!(h0 & hp)) {
                        const int h1 = h0 | hp;
                        const float2 a0 = a[h0], a1 = a[h1];
                        a[h0] = cadd(cmul(u00, a0), cmul(u01, a1));
                        a[h1] = cadd(cmul(u10, a0), cmul(u11, a1));
                    }
                }
            } else {
                #pragma unroll
                for (int h = 0; h < 4; h++) {
                    float2 p;
                    p.x = __shfl_xor_sync(0xffffffffu, a[h].x, b);
                    p.y = __shfl_xor_sync(0xffffffffu, a[h].y, b);
                    const float2 s = a[h];
                    if (lane & b) a[h] = cadd(cmul(u10, p), cmul(u11, s));
                    else          a[h] = cadd(cmul(u00, s), cmul(u01, p));
                }
            }
        }
        const int r = (l % (NQ - 1)) + 1;
        #pragma unroll
        for (int c = 0; c < NQ; c++) {
            const int t = (c + r) % NQ;
            const int cb = 1 << (6 - c);
            const int tb = 1 << (6 - t);
            if (tb >= 32) {
                const int hb = tb >> 5;
                if (cb >= 32) {
                    const int chb = cb >> 5;
                    #pragma unroll
                    for (int h0 = 0; h0 < 4; h0++)
                        if (!(h0 & hb) && (h0 & chb)) {
                            const float2 tmp = a[h0];
                            a[h0] = a[h0 | hb];
                            a[h0 | hb] = tmp;
                        }
                } else {
                    if (lane & cb) {
                        #pragma unroll
                        for (int h0 = 0; h0 < 4; h0++)
                            if (!(h0 & hb)) {
                                const float2 tmp = a[h0];
                                a[h0] = a[h0 | hb];
                                a[h0 | hb] = tmp;
                            }
                    }
                }
            } else {
                #pragma unroll
                for (int h = 0; h < 4; h++) {
                    float2 p;
                    p.x = __shfl_xor_sync(0xffffffffu, a[h].x, tb);
                    p.y = __shfl_xor_sync(0xffffffffu, a[h].y, tb);
                    const bool ctrl = (cb >= 32) ? ((h & (cb >> 5)) != 0)
                                                 : ((lane & cb) != 0);
                    if (ctrl) a[h] = p;
                }
            }
        }
    }
    #pragma unroll
    for (int h = 0; h < 4; h++) {
        const int idx = h * 32 + lane;
        g_U[idx * DIM + j] = a[h];
        g_UT[j * DIM + idx] = a[h];
    }
}

// ---------------------------------------------------------------------------
// Kernel 2: A[i][j] = sum_k d_k * Re(conj(U[k][i]) U[k][j]); fp16.
// Also resets the dynamic tile counter for the main kernel.
// ---------------------------------------------------------------------------
__global__ void build_w_kernel() {
    __shared__ float2 ui[DIM];
    const int i = blockIdx.x;
    const int j = threadIdx.x;
    if (i == 0 && j == 0) g_ctr = 0;
    ui[j] = g_UT[i * DIM + j];
    __syncthreads();
    float acc = 0.f;
    #pragma unroll 4
    for (int k = 0; k < DIM; k++) {
        const float dk = (((k >> 6) ^ k) & 1) ? -1.f : 1.f;
        const float2 uj = g_U[k * DIM + j];
        acc += dk * (ui[k].x * uj.x + ui[k].y * uj.y);
    }
    g_W[i * DIM + j] = __float2half_rn(acc);
}

// ---------------------------------------------------------------------------
// Main kernel: ONE MMA segment y1 = A*xhi; symmetry gives
// x^T A x = (xhi + 2*xlo)^T y1 + O(2^-22). TILE_M=64, occ 2, dynamic tiles.
// ---------------------------------------------------------------------------
#define SM_ZHI 0
#define SM_ZLO 17408
#define SM_W   34816
#define SM_PD  69632
#define SM_PS  70656
#define SM_NEXT 71680
#define SM_TOTAL 71696

__device__ __forceinline__ void ldsm4(uint32_t& r0, uint32_t& r1, uint32_t& r2,
                                      uint32_t& r3, uint32_t addr) {
    asm volatile("ldmatrix.sync.aligned.m8n8.x4.shared.b16 {%0,%1,%2,%3}, [%4];"
                 : "=r"(r0), "=r"(r1), "=r"(r2), "=r"(r3) : "r"(addr));
}
__device__ __forceinline__ void mma16816(float* d, const uint32_t* a, const uint32_t* b) {
    asm volatile(
        "mma.sync.aligned.m16n8k16.row.col.f32.f16.f16.f32 "
        "{%0,%1,%2,%3}, {%4,%5,%6,%7}, {%8,%9}, {%0,%1,%2,%3};"
        : "+f"(d[0]), "+f"(d[1]), "+f"(d[2]), "+f"(d[3])
        : "r"(a[0]), "r"(a[1]), "r"(a[2]), "r"(a[3]), "r"(b[0]), "r"(b[1]));
}
__device__ __forceinline__ uint32_t pack2h(float a, float b) {
    const __half2 h = __floats2half2_rn(a, b);
    return *(const uint32_t*)&h;
}

__global__ void __launch_bounds__(NTHREADS, 2)
vqa_main_kernel(const float* __restrict__ x, float* __restrict__ out, int ntiles) {
    extern __shared__ char smem[];
    const uint32_t sbase = (uint32_t)__cvta_generic_to_shared(smem);
    float* pd = (float*)(smem + SM_PD);
    float* ps = (float*)(smem + SM_PS);
    int* nxt = (int*)(smem + SM_NEXT);

    const int tid = threadIdx.x;
    const int lane = tid & 31;
    const int wid = tid >> 5;
    const int mi = wid & 1;   // m-stripe (32 rows)
    const int nh = wid >> 1;  // n-quarter (32 cols)

    // ---- load W (fp16 A) into padded smem, once per CTA ----
    {
        const uint2* w_g = (const uint2*)g_W;
        for (int idx = tid; idx < DIM * 32; idx += NTHREADS) {
            const int i = idx >> 5, c = idx & 31;
            *(uint2*)(smem + SM_W + i * (KPAD * 2) + c * 8) = w_g[idx];
        }
    }

    // ldmatrix lane base addresses (bytes)
    const uint32_t abase = sbase + SM_ZHI +
        (uint32_t)(((32 * mi + (lane & 15)) * KPAD + 8 * (lane >> 4)) * 2);
    const int rowL = (lane & 7) + ((lane >> 4) & 1) * 8;
    const int kL = ((lane >> 3) & 1) * 8;
    const uint32_t bbase = sbase + SM_W +
        (uint32_t)(((32 * nh + rowL) * KPAD + kL) * 2);

    // ---- first tile via dynamic counter ----
    if (tid == 0) *nxt = atomicAdd(&g_ctr, 1);
    __syncthreads();
    int tile = *nxt;

    while (tile < ntiles) {
        // prefetch next tile index (consumed after the final barrier)
        if (tid == 0) *nxt = atomicAdd(&g_ctr, 1);

        // ---- phase 1: load + convert (pure streaming) ----
        const float4* xt = (const float4*)x + (size_t)tile * (TILE_M * 32);
        #pragma unroll
        for (int rr = 0; rr < 8; rr++) {
            const int row = wid * 8 + rr;
            const float4 vv = xt[row * 32 + lane];
            const float hx = __half2float(__float2half_rn(vv.x));
            const float hy = __half2float(__float2half_rn(vv.y));
            const float hz = __half2float(__float2half_rn(vv.z));
            const float hw = __half2float(__float2half_rn(vv.w));
            *(uint2*)(smem + SM_ZHI + row * (KPAD * 2) + lane * 8) =
                make_uint2(pack2h(hx, hy), pack2h(hz, hw));
            *(uint2*)(smem + SM_ZLO + row * (KPAD * 2) + lane * 8) =
                make_uint2(pack2h(vv.x - hx, vv.y - hy), pack2h(vv.z - hz, vv.w - hw));
        }
        __syncthreads();

        // ---- phase 2: GEMM, single segment y1 = A * xhi ----
        float d[2][4][4];
        #pragma unroll
        for (int mt = 0; mt < 2; mt++)
            #pragma unroll
            for (int nt = 0; nt < 4; nt++)
                #pragma unroll
                for (int q = 0; q < 4; q++) d[mt][nt][q] = 0.f;

        #pragma unroll
        for (int kk = 0; kk < 8; kk++) {
            const uint32_t ko = (uint32_t)(kk * 32);  // 16 elems * 2B
            uint32_t ah0[4], ah1[4];
            ldsm4(ah0[0], ah0[1], ah0[2], ah0[3], abase + ko);
            ldsm4(ah1[0], ah1[1], ah1[2], ah1[3], abase + ko + 16 * KPAD * 2);
            uint32_t bh[2][4];
            #pragma unroll
            for (int ntp = 0; ntp < 2; ntp++) {
                const uint32_t bo = bbase + ko + (uint32_t)(ntp * 16 * KPAD * 2);
                ldsm4(bh[ntp][0], bh[ntp][1], bh[ntp][2], bh[ntp][3], bo);
            }
            #pragma unroll
            for (int ntp = 0; ntp < 2; ntp++) {
                mma16816(d[0][2 * ntp + 0], ah0, &bh[ntp][0]);
                mma16816(d[0][2 * ntp + 1], ah0, &bh[ntp][2]);
                mma16816(d[1][2 * ntp + 0], ah1, &bh[ntp][0]);
                mma16816(d[1][2 * ntp + 1], ah1, &bh[ntp][2]);
            }
        }

        // ---- phase 3: epilogue — num = (xhi+2*xlo).y1 ; den = (xhi+xlo)^2 ----
        const int tq = lane & 3;
        const int tr = lane >> 2;
        float racc[4] = {0.f, 0.f, 0.f, 0.f};
        float sacc[4] = {0.f, 0.f, 0.f, 0.f};
        #pragma unroll
        for (int mt = 0; mt < 2; mt++) {
            const int row0 = 32 * mi + 16 * mt + tr;
            #pragma unroll
            for (int nt = 0; nt < 4; nt++) {
                const int c = 32 * nh + 8 * nt + 2 * tq;
                const int o0 = (row0 * KPAD + c) * 2;
                const int o1 = ((row0 + 8) * KPAD + c) * 2;
                const float2 h0 = __half22float2(*(__half2*)(smem + SM_ZHI + o0));
                const float2 l0 = __half22float2(*(__half2*)(smem + SM_ZLO + o0));
                const float2 h1 = __half22float2(*(__half2*)(smem + SM_ZHI + o1));
                const float2 l1 = __half22float2(*(__half2*)(smem + SM_ZLO + o1));
                const float x0a = h0.x + l0.x, x0b = h0.y + l0.y;
                const float x1a = h1.x + l1.x, x1b = h1.y + l1.y;
                // weights: xhi + 2*xlo = x + xlo
                const float w0a = x0a + l0.x, w0b = x0b + l0.y;
                const float w1a = x1a + l1.x, w1b = x1b + l1.y;
                racc[2 * mt]     += d[mt][nt][0] * w0a + d[mt][nt][1] * w0b;
                racc[2 * mt + 1] += d[mt][nt][2] * w1a + d[mt][nt][3] * w1b;
                sacc[2 * mt]     += x0a * x0a + x0b * x0b;
                sacc[2 * mt + 1] += x1a * x1a + x1b * x1b;
            }
        }
        #pragma unroll
        for (int q = 0; q < 4; q++) {
            racc[q] += __shfl_xor_sync(0xffffffffu, racc[q], 1);
            racc[q] += __shfl_xor_sync(0xffffffffu, racc[q], 2);
            sacc[q] += __shfl_xor_sync(0xffffffffu, sacc[q], 1);
            sacc[q] += __shfl_xor_sync(0xffffffffu, sacc[q], 2);
        }
        if (tq == 0) {
            #pragma unroll
            for (int q = 0; q < 4; q++) {
                const int row = 32 * mi + 8 * q + tr;
                pd[row * 4 + nh] = racc[q];
                ps[row * 4 + nh] = sacc[q];
            }
        }
        __syncthreads();
        int newtile = *nxt;   // read between barriers (write happens after next one)
        if (tid < TILE_M) {
            const float num = pd[tid * 4] + pd[tid * 4 + 1] +
                              pd[tid * 4 + 2] + pd[tid * 4 + 3];
            const float den = ps[tid * 4] + ps[tid * 4 + 1] +
                              ps[tid * 4 + 2] + ps[tid * 4 + 3];
            out[(size_t)tile * TILE_M + tid] = num / den;
        }
        __syncthreads();
        tile = newtile;
    }
}

// ---------------------------------------------------------------------------
extern "C" void kernel_launch(void* const* d_in, const int* in_sizes, int n_in,
                              void* d_out, int out_size) {
    const float* x = (const float*)d_in[0];
    const float* w = (const float*)d_in[1];
    float* out = (float*)d_out;

    cudaFuncSetAttribute(vqa_main_kernel,
                         cudaFuncAttributeMaxDynamicSharedMemorySize, SM_TOTAL);
    cudaFuncSetAttribute(vqa_main_kernel,
                         cudaFuncAttributePreferredSharedMemoryCarveout, 100);

    build_u_kernel<<<DIM / 4, 128>>>(w);
    build_w_kernel<<<DIM, DIM>>>();

    const int rows = in_sizes[0] / DIM;
    const int ntiles = rows / TILE_M;
    vqa_main_kernel<<<304, NTHREADS, SM_TOTAL>>>(x, out, ntiles);
}